// round 4
// baseline (speedup 1.0000x reference)
#include <cuda_runtime.h>

// Problem constants
#define BB      2
#define TT      2048
#define NH      12
#define DH      64
#define CC      768      // d_model
#define C3      2304     // 3*d_model
#define MM      (BB*TT)  // 4096 rows

// Scratch (device globals — no runtime allocation allowed)
__device__ float g_qkv[(size_t)MM * C3];     // [4096, 2304]  (tf32-rounded values)
__device__ float g_att[(size_t)MM * CC];     // [4096, 768]   (tf32-rounded values)
__device__ float g_xr[(size_t)MM * CC];      // x rounded
__device__ float g_wqkvr[(size_t)CC * C3];   // Wqkv rounded
__device__ float g_woutr[(size_t)CC * CC];   // Wout rounded

// ---------------------------------------------------------------------------
// helpers
// ---------------------------------------------------------------------------
__device__ __forceinline__ unsigned f2tf(float f) {
    unsigned u; asm("cvt.rna.tf32.f32 %0, %1;" : "=r"(u) : "f"(f)); return u;
}
__device__ __forceinline__ float ex2f(float x) {
    float r; asm("ex2.approx.f32 %0, %1;" : "=f"(r) : "f"(x)); return r;
}
__device__ __forceinline__ void mma_tf32(float c[4], const unsigned a[4], const unsigned b[2]) {
    asm volatile(
        "mma.sync.aligned.m16n8k8.row.col.f32.tf32.tf32.f32 "
        "{%0,%1,%2,%3},{%4,%5,%6,%7},{%8,%9},{%0,%1,%2,%3};"
        : "+f"(c[0]), "+f"(c[1]), "+f"(c[2]), "+f"(c[3])
        : "r"(a[0]), "r"(a[1]), "r"(a[2]), "r"(a[3]), "r"(b[0]), "r"(b[1]));
}
__device__ __forceinline__ void cp16(void* dst_smem, const void* src) {
    unsigned d = (unsigned)__cvta_generic_to_shared(dst_smem);
    asm volatile("cp.async.cg.shared.global [%0], [%1], 16;" :: "r"(d), "l"(src));
}
__device__ __forceinline__ void cp_commit() {
    asm volatile("cp.async.commit_group;");
}
template<int N> __device__ __forceinline__ void cp_wait() {
    asm volatile("cp.async.wait_group %0;" :: "n"(N));
}

// ---------------------------------------------------------------------------
// Pre-pass: round fp32 array to tf32 (rna) in one shot.
// ---------------------------------------------------------------------------
__global__ void round_tf32_kernel(const float* __restrict__ in, float* __restrict__ out, int n4)
{
    int i = blockIdx.x * blockDim.x + threadIdx.x;
    if (i < n4) {
        float4 v = ((const float4*)in)[i];
        uint4 u = make_uint4(f2tf(v.x), f2tf(v.y), f2tf(v.z), f2tf(v.w));
        ((float4*)out)[i] = *(float4*)&u;
    }
}

// ---------------------------------------------------------------------------
// TF32 tensor-core GEMM with bias, cp.async 3-stage pipeline, 1 barrier/iter.
// C[M,N] = A[M,K] @ B[K,N] + bias[N]. Inputs pre-rounded to tf32.
// 128x128 block tile, BK=32, 256 threads (8 warps), warp tile 64x32.
// Dynamic smem: 3 stages x (A[128][36] + B[32][136]) = 107520 B.
// ---------------------------------------------------------------------------
#define GA_W   (128*36)      // A stage words
#define GB_W   (32*136)      // B stage words
#define GSTAGE (GA_W + GB_W) // 8960 words
#define GEMM_SMEM (3 * GSTAGE * 4)

template<bool ROUND_OUT>
__global__ __launch_bounds__(256, 2)
void gemm_tf32_ca(const float* __restrict__ A, const float* __restrict__ B,
                  const float* __restrict__ bias, float* __restrict__ C,
                  int M, int N, int K)
{
    extern __shared__ unsigned smg[];

    const int tid  = threadIdx.x;
    const int lane = tid & 31;
    const int w    = tid >> 5;
    const int wm   = (w >> 2) * 64;
    const int wn   = (w & 3) * 32;
    const int g    = lane >> 2;
    const int tig  = lane & 3;
    const int rowBase = blockIdx.y * 128;
    const int colBase = blockIdx.x * 128;

    float acc[4][4][4];
#pragma unroll
    for (int mt = 0; mt < 4; mt++)
#pragma unroll
        for (int nt = 0; nt < 4; nt++)
#pragma unroll
            for (int j = 0; j < 4; j++) acc[mt][nt][j] = 0.f;

    auto loadTile = [&](int k0, int s) {
        unsigned* As = smg + s * GSTAGE;
        unsigned* Bs = smg + s * GSTAGE + GA_W;
#pragma unroll
        for (int i = 0; i < 4; i++) {
            int c = tid + i * 256;
            int r = c >> 3, c4 = c & 7;
            cp16(&As[r * 36 + c4 * 4], A + (size_t)(rowBase + r) * K + k0 + c4 * 4);
        }
#pragma unroll
        for (int i = 0; i < 4; i++) {
            int c = tid + i * 256;
            int r = c >> 5, c4 = c & 31;
            cp16(&Bs[r * 136 + c4 * 4], B + (size_t)(k0 + r) * N + colBase + c4 * 4);
        }
    };

    loadTile(0, 0);  cp_commit();
    loadTile(32, 1); cp_commit();

    int buf = 0;
    for (int k0 = 0; k0 < K; k0 += 32) {
        cp_wait<1>();
        __syncthreads();                     // stage buf ready; buf-1 compute done

        if (k0 + 64 < K) loadTile(k0 + 64, buf == 0 ? 2 : buf - 1);
        cp_commit();                          // (empty group near the tail is fine)

        unsigned (*As)[36]  = (unsigned(*)[36])(smg + buf * GSTAGE);
        unsigned (*Bs)[136] = (unsigned(*)[136])(smg + buf * GSTAGE + GA_W);

#pragma unroll
        for (int ks = 0; ks < 4; ks++) {
            unsigned af[4][4], bf[4][2];
#pragma unroll
            for (int mt = 0; mt < 4; mt++) {
                int m = wm + mt * 16 + g;
                af[mt][0] = As[m][ks * 8 + tig];
                af[mt][1] = As[m + 8][ks * 8 + tig];
                af[mt][2] = As[m][ks * 8 + tig + 4];
                af[mt][3] = As[m + 8][ks * 8 + tig + 4];
            }
#pragma unroll
            for (int nt = 0; nt < 4; nt++) {
                int n = wn + nt * 8 + g;
                bf[nt][0] = Bs[ks * 8 + tig][n];
                bf[nt][1] = Bs[ks * 8 + tig + 4][n];
            }
#pragma unroll
            for (int mt = 0; mt < 4; mt++)
#pragma unroll
                for (int nt = 0; nt < 4; nt++)
                    mma_tf32(acc[mt][nt], af[mt], bf[nt]);
        }
        buf = (buf == 2) ? 0 : buf + 1;
    }

#pragma unroll
    for (int mt = 0; mt < 4; mt++) {
        int r0 = rowBase + wm + mt * 16 + g;
#pragma unroll
        for (int nt = 0; nt < 4; nt++) {
            int c = colBase + wn + nt * 8 + 2 * tig;
            float2 b2 = *(const float2*)(bias + c);
            float v00 = acc[mt][nt][0] + b2.x, v01 = acc[mt][nt][1] + b2.y;
            float v10 = acc[mt][nt][2] + b2.x, v11 = acc[mt][nt][3] + b2.y;
            float2 o0, o1;
            if (ROUND_OUT) {
                o0.x = __uint_as_float(f2tf(v00)); o0.y = __uint_as_float(f2tf(v01));
                o1.x = __uint_as_float(f2tf(v10)); o1.y = __uint_as_float(f2tf(v11));
            } else {
                o0.x = v00; o0.y = v01; o1.x = v10; o1.y = v11;
            }
            *(float2*)(C + (size_t)r0 * N + c)       = o0;
            *(float2*)(C + (size_t)(r0 + 8) * N + c) = o1;
        }
    }
}

// ---------------------------------------------------------------------------
// Causal flash attention, TF32 tensor cores, cp.async double-buffered K/V.
// Block: 128 queries (one (b,h)), 8 warps x 16 queries. Key tiles of 64.
// qkv holds tf32-rounded values. Output written tf32-rounded.
// Dyn smem: QP[128][68] | 2 x (Ks[64][68] + Vs[64][72]) = 106496 B.
// ---------------------------------------------------------------------------
#define QP_W    (128*68)
#define KS_W    (64*68)
#define VS_W    (64*72)
#define FSTAGE  (KS_W + VS_W)
#define FLASH_SMEM ((QP_W + 2*FSTAGE) * 4)

__global__ __launch_bounds__(256, 2)
void flash_tf32(const float* __restrict__ qkv, float* __restrict__ out)
{
    extern __shared__ unsigned sm[];
    unsigned (*QP)[68] = (unsigned(*)[68])sm;

    const int b    = blockIdx.z;
    const int h    = blockIdx.y;
    const int qb   = gridDim.x - 1 - blockIdx.x;   // heavy blocks first
    const int tid  = threadIdx.x;
    const int lane = tid & 31;
    const int w    = tid >> 5;
    const int g    = lane >> 2;
    const int tig  = lane & 3;
    const int m0   = w * 16;

    const float SC = 0.125f * 1.44269504088896341f;  // scale * log2(e)

    auto loadKV = [&](int kb, int s) {
        unsigned* Ks = sm + QP_W + s * FSTAGE;
        unsigned* Vs = Ks + KS_W;
        const float* kp = qkv + (size_t)(b * TT + kb * 64) * C3 + CC + h * DH;
#pragma unroll
        for (int i = 0; i < 4; i++) {
            int idx = tid + i * 256;           // 0..1023
            int r = idx >> 4, c4 = idx & 15;
            const float* rp = kp + (size_t)r * C3 + c4 * 4;
            cp16(&Ks[r * 68 + c4 * 4], rp);
            cp16(&Vs[r * 72 + c4 * 4], rp + CC);
        }
    };

    loadKV(0, 0);
    cp_commit();

    // ---- load Q tile (raw, pre-rounded): 128 rows ----
    {
        const float* qp = qkv + (size_t)(b * TT + qb * 128) * C3 + h * DH;
#pragma unroll
        for (int i = 0; i < 8; i++) {
            int idx = tid + i * 256;           // 0..2047
            int r = idx >> 4, c4 = idx & 15;
            *(float4*)&QP[r][c4 * 4] = *(const float4*)(qp + (size_t)r * C3 + c4 * 4);
        }
    }
    __syncthreads();

    // ---- persistent Q fragments ----
    unsigned qf[8][4];
#pragma unroll
    for (int kt = 0; kt < 8; kt++) {
        qf[kt][0] = QP[m0 + g][kt * 8 + tig];
        qf[kt][1] = QP[m0 + 8 + g][kt * 8 + tig];
        qf[kt][2] = QP[m0 + g][kt * 8 + tig + 4];
        qf[kt][3] = QP[m0 + 8 + g][kt * 8 + tig + 4];
    }

    float o[8][4];
#pragma unroll
    for (int nt = 0; nt < 8; nt++)
#pragma unroll
        for (int j = 0; j < 4; j++) o[nt][j] = 0.f;

    float mr0 = -1e30f, mr1 = -1e30f, l0 = 0.f, l1 = 0.f;
    const int qg0 = qb * 128 + m0 + g;     // global row of c0/c1
    const int qg1 = qg0 + 8;               // global row of c2/c3

    const int klast  = 2 * qb + 1;                    // last key tile loaded
    const int kend_w = 2 * qb + (m0 >= 64 ? 1 : 0);   // this warp's last tile

    int buf = 0;
    for (int kb = 0; kb <= klast; kb++) {
        if (kb < klast) { loadKV(kb + 1, buf ^ 1); cp_commit(); cp_wait<1>(); }
        else            { cp_wait<0>(); }
        __syncthreads();

        if (kb <= kend_w) {
            unsigned (*Ks)[68] = (unsigned(*)[68])(sm + QP_W + buf * FSTAGE);
            unsigned (*Vs)[72] = (unsigned(*)[72])(sm + QP_W + buf * FSTAGE + KS_W);

            // ---- S = Q K^T (then scale) ----
            float s[8][4];
#pragma unroll
            for (int nt = 0; nt < 8; nt++) {
                s[nt][0] = s[nt][1] = s[nt][2] = s[nt][3] = 0.f;
#pragma unroll
                for (int kt = 0; kt < 8; kt++) {
                    unsigned bb[2];
                    bb[0] = Ks[nt * 8 + g][kt * 8 + tig];
                    bb[1] = Ks[nt * 8 + g][kt * 8 + tig + 4];
                    mma_tf32(s[nt], qf[kt], bb);
                }
                s[nt][0] *= SC; s[nt][1] *= SC; s[nt][2] *= SC; s[nt][3] *= SC;
            }

            // ---- causal mask (this warp's diagonal tile only) ----
            if (kb == kend_w) {
#pragma unroll
                for (int nt = 0; nt < 8; nt++) {
                    int kg = kb * 64 + nt * 8 + 2 * tig;
                    if (kg > qg0)     s[nt][0] = -1e30f;
                    if (kg + 1 > qg0) s[nt][1] = -1e30f;
                    if (kg > qg1)     s[nt][2] = -1e30f;
                    if (kg + 1 > qg1) s[nt][3] = -1e30f;
                }
            }

            // ---- online softmax (base-2) ----
            float vm0 = -1e30f, vm1 = -1e30f;
#pragma unroll
            for (int nt = 0; nt < 8; nt++) {
                vm0 = fmaxf(vm0, fmaxf(s[nt][0], s[nt][1]));
                vm1 = fmaxf(vm1, fmaxf(s[nt][2], s[nt][3]));
            }
            vm0 = fmaxf(vm0, __shfl_xor_sync(0xffffffffu, vm0, 1));
            vm0 = fmaxf(vm0, __shfl_xor_sync(0xffffffffu, vm0, 2));
            vm1 = fmaxf(vm1, __shfl_xor_sync(0xffffffffu, vm1, 1));
            vm1 = fmaxf(vm1, __shfl_xor_sync(0xffffffffu, vm1, 2));

            float mn0 = fmaxf(mr0, vm0), mn1 = fmaxf(mr1, vm1);
            float corr0 = ex2f(mr0 - mn0), corr1 = ex2f(mr1 - mn1);
            mr0 = mn0; mr1 = mn1;

            float sum0 = 0.f, sum1 = 0.f;
#pragma unroll
            for (int nt = 0; nt < 8; nt++) {
                s[nt][0] = ex2f(s[nt][0] - mn0);
                s[nt][1] = ex2f(s[nt][1] - mn0);
                s[nt][2] = ex2f(s[nt][2] - mn1);
                s[nt][3] = ex2f(s[nt][3] - mn1);
                sum0 += s[nt][0] + s[nt][1];
                sum1 += s[nt][2] + s[nt][3];
            }
            sum0 += __shfl_xor_sync(0xffffffffu, sum0, 1);
            sum0 += __shfl_xor_sync(0xffffffffu, sum0, 2);
            sum1 += __shfl_xor_sync(0xffffffffu, sum1, 1);
            sum1 += __shfl_xor_sync(0xffffffffu, sum1, 2);
            l0 = l0 * corr0 + sum0;
            l1 = l1 * corr1 + sum1;

#pragma unroll
            for (int nt = 0; nt < 8; nt++) {
                o[nt][0] *= corr0; o[nt][1] *= corr0;
                o[nt][2] *= corr1; o[nt][3] *= corr1;
            }

            // ---- stage P into QP (warp-local rows) ----
            __syncwarp();
#pragma unroll
            for (int nt = 0; nt < 8; nt++) {
                uint2 u0 = make_uint2(f2tf(s[nt][0]), f2tf(s[nt][1]));
                uint2 u1 = make_uint2(f2tf(s[nt][2]), f2tf(s[nt][3]));
                *(uint2*)&QP[m0 + g][nt * 8 + 2 * tig]     = u0;
                *(uint2*)&QP[m0 + 8 + g][nt * 8 + 2 * tig] = u1;
            }
            __syncwarp();

            // ---- O += P V ----
#pragma unroll
            for (int kt = 0; kt < 8; kt++) {
                unsigned pa[4];
                pa[0] = QP[m0 + g][kt * 8 + tig];
                pa[1] = QP[m0 + 8 + g][kt * 8 + tig];
                pa[2] = QP[m0 + g][kt * 8 + tig + 4];
                pa[3] = QP[m0 + 8 + g][kt * 8 + tig + 4];
#pragma unroll
                for (int nt = 0; nt < 8; nt++) {
                    unsigned bb[2];
                    bb[0] = Vs[kt * 8 + tig][nt * 8 + g];
                    bb[1] = Vs[kt * 8 + tig + 4][nt * 8 + g];
                    mma_tf32(o[nt], pa, bb);
                }
            }
        }
        __syncthreads();   // all warps done with K/V `buf` before refill
        buf ^= 1;
    }

    // ---- normalize and write out (tf32-rounded for the next GEMM) ----
    const float inv0 = 1.f / l0, inv1 = 1.f / l1;
    float* op0 = out + (size_t)(b * TT + qb * 128 + m0 + g) * CC + h * DH;
    float* op1 = op0 + (size_t)8 * CC;
#pragma unroll
    for (int nt = 0; nt < 8; nt++) {
        float2 r0, r1;
        r0.x = __uint_as_float(f2tf(o[nt][0] * inv0));
        r0.y = __uint_as_float(f2tf(o[nt][1] * inv0));
        r1.x = __uint_as_float(f2tf(o[nt][2] * inv1));
        r1.y = __uint_as_float(f2tf(o[nt][3] * inv1));
        *(float2*)(op0 + nt * 8 + 2 * tig) = r0;
        *(float2*)(op1 + nt * 8 + 2 * tig) = r1;
    }
}

// ---------------------------------------------------------------------------
// kernel_launch
// ---------------------------------------------------------------------------
extern "C" void kernel_launch(void* const* d_in, const int* in_sizes, int n_in,
                              void* d_out, int out_size)
{
    const float* x    = (const float*)d_in[0];
    // d_in[1] = mask (static causal; unused)
    const float* Wqkv = (const float*)d_in[2];
    const float* bqkv = (const float*)d_in[3];
    const float* Wout = (const float*)d_in[4];
    const float* bout = (const float*)d_in[5];
    float* out = (float*)d_out;

    float* qkv;   cudaGetSymbolAddress((void**)&qkv,   g_qkv);
    float* att;   cudaGetSymbolAddress((void**)&att,   g_att);
    float* xr;    cudaGetSymbolAddress((void**)&xr,    g_xr);
    float* wqkvr; cudaGetSymbolAddress((void**)&wqkvr, g_wqkvr);
    float* woutr; cudaGetSymbolAddress((void**)&woutr, g_woutr);

    static bool configured = false;
    if (!configured) {
        cudaFuncSetAttribute(gemm_tf32_ca<true>,
                             cudaFuncAttributeMaxDynamicSharedMemorySize, GEMM_SMEM);
        cudaFuncSetAttribute(gemm_tf32_ca<false>,
                             cudaFuncAttributeMaxDynamicSharedMemorySize, GEMM_SMEM);
        cudaFuncSetAttribute(flash_tf32,
                             cudaFuncAttributeMaxDynamicSharedMemorySize, FLASH_SMEM);
        configured = true;
    }

    // 0) round inputs to tf32 once
    round_tf32_kernel<<<(MM * CC / 4 + 255) / 256, 256>>>(x, xr, MM * CC / 4);
    round_tf32_kernel<<<(CC * C3 / 4 + 255) / 256, 256>>>(Wqkv, wqkvr, CC * C3 / 4);
    round_tf32_kernel<<<(CC * CC / 4 + 255) / 256, 256>>>(Wout, woutr, CC * CC / 4);

    // 1) QKV projection: [4096,768] @ [768,2304] + bias  (rounded output)
    {
        dim3 grid(C3 / 128, MM / 128);
        gemm_tf32_ca<true><<<grid, 256, GEMM_SMEM>>>(xr, wqkvr, bqkv, qkv, MM, C3, CC);
    }
    // 2) Causal multi-head attention (rounded output)
    {
        dim3 grid(TT / 128, NH, BB);
        flash_tf32<<<grid, 256, FLASH_SMEM>>>(qkv, att);
    }
    // 3) Output projection: [4096,768] @ [768,768] + bias (exact fp32 output)
    {
        dim3 grid(CC / 128, MM / 128);
        gemm_tf32_ca<false><<<grid, 256, GEMM_SMEM>>>(att, woutr, bout, out, MM, CC, CC);
    }
}